// round 6
// baseline (speedup 1.0000x reference)
#include <cuda_runtime.h>
#include <stdint.h>

// Problem constants: B=16, L=4096, H=768 (fp32)
#define B_ 16
#define L_ 4096
#define H_ 768
#define H4 (H_ / 4)            // 192 float4 lanes per row
#define TOK_PER_BLK 8          // tokens per block tile (smem-staged output)
#define CH 8                   // rows prefetched per chunk (per-thread MLP)
#define BLOCKS_PER_BATCH (L_ / TOK_PER_BLK)  // 512

__global__ __launch_bounds__(H4)
void token_segment_sum_kernel(const float* __restrict__ x,
                              const int*   __restrict__ seg,
                              float*       __restrict__ out)
{
    const int b    = blockIdx.x / BLOCKS_PER_BATCH;
    const int tile = blockIdx.x % BLOCKS_PER_BATCH;
    const int j0   = tile * TOK_PER_BLK;

    const int* __restrict__ segb = seg + b * L_;

    __shared__ int    bnd[TOK_PER_BLK + 1];
    __shared__ float4 obuf[TOK_PER_BLK * H4];   // staged output tile (24 KB)

    const int t = threadIdx.x;   // 0..191 (float4 lane)
    if (t <= TOK_PER_BLK) {
        // lower_bound: first index i with segb[i] >= (j0 + t)
        const int target = j0 + t;
        int lo = 0, hi = L_;
        #pragma unroll 1
        while (lo < hi) {
            int mid = (lo + hi) >> 1;
            if (segb[mid] < target) lo = mid + 1; else hi = mid;
        }
        bnd[t] = lo;
    }
    __syncthreads();

    const float4* __restrict__ xb =
        reinterpret_cast<const float4*>(x + (size_t)b * L_ * H_);
    float4* __restrict__ ob =
        reinterpret_cast<float4*>(out + (size_t)b * L_ * H_);

    const int s0 = bnd[0];
    const int s1 = bnd[TOK_PER_BLK];

    int j = 0;

    // tokens empty at the very start (bnd[j+1] == s0) -> zero rows in smem
    #pragma unroll 1
    while (j < TOK_PER_BLK && bnd[j + 1] == s0) {
        obuf[j * H4 + t] = make_float4(0.f, 0.f, 0.f, 0.f);
        j++;
    }

    float4 acc = make_float4(0.f, 0.f, 0.f, 0.f);

    // PHASE 1: pure read stream over contiguous rows [s0, s1), CH-deep MLP.
    // Completed tokens land in smem, not gmem -> no read/write interleave.
    #pragma unroll 1
    for (int base = s0; base < s1; base += CH) {
        const int n = min(CH, s1 - base);

        float4 v[CH];
        #pragma unroll
        for (int i = 0; i < CH; i++)
            if (i < n)
                v[i] = __ldg(&xb[(size_t)(base + i) * H4 + t]);

        #pragma unroll
        for (int i = 0; i < CH; i++) {
            if (i < n) {
                acc.x += v[i].x; acc.y += v[i].y;
                acc.z += v[i].z; acc.w += v[i].w;
                const int pos1 = base + i + 1;
                // flush every token ending exactly here (empty tokens get
                // zero since acc resets between equal boundaries)
                #pragma unroll 1
                while (j < TOK_PER_BLK && bnd[j + 1] == pos1) {
                    obuf[j * H4 + t] = acc;
                    acc = make_float4(0.f, 0.f, 0.f, 0.f);
                    j++;
                }
            }
        }
    }

    __syncthreads();

    // PHASE 2: pure write burst — 8 independent STGs per thread, 24 KB/block.
    #pragma unroll
    for (int r = 0; r < TOK_PER_BLK; r++)
        ob[(size_t)(j0 + r) * H4 + t] = obuf[r * H4 + t];
}

extern "C" void kernel_launch(void* const* d_in, const int* in_sizes, int n_in,
                              void* d_out, int out_size)
{
    const float* x   = (const float*)d_in[0];   // sequence_output  [B, L, H] f32
    const int*   seg = (const int*)  d_in[1];   // wordpiece_to_token [B, L] i32
    float*       out = (float*)d_out;           // [B, L, H] f32

    dim3 grid(B_ * BLOCKS_PER_BATCH);           // 8192 blocks
    dim3 block(H4);                             // 192 threads
    token_segment_sum_kernel<<<grid, block>>>(x, seg, out);
}

// round 7
// speedup vs baseline: 1.0894x; 1.0894x over previous
#include <cuda_runtime.h>
#include <stdint.h>

// Problem constants: B=16, L=4096, H=768 (fp32)
#define B_ 16
#define L_ 4096
#define H_ 768
#define H4 (H_ / 4)            // 192 float4 lanes per row
#define TOK_PER_BLK 16         // tokens per tile
#define CH 8                   // rows prefetched per chunk (per-thread MLP)
#define TILES_PER_BATCH (L_ / TOK_PER_BLK)      // 256
#define NUM_TILES (B_ * TILES_PER_BATCH)        // 4096
#define GRID_BLOCKS (148 * 5)                   // one full residency -> 1 wave

__global__ __launch_bounds__(H4)
void token_segment_sum_kernel(const float* __restrict__ x,
                              const int*   __restrict__ seg,
                              float*       __restrict__ out)
{
    __shared__ int bnd[TOK_PER_BLK + 1];
    const int t = threadIdx.x;   // 0..191 (float4 lane)

    // persistent: each block sweeps tiles bid, bid+740, bid+1480, ...
    #pragma unroll 1
    for (int tileIdx = blockIdx.x; tileIdx < NUM_TILES; tileIdx += GRID_BLOCKS)
    {
        const int b    = tileIdx / TILES_PER_BATCH;
        const int tile = tileIdx % TILES_PER_BATCH;
        const int j0   = tile * TOK_PER_BLK;

        const int* __restrict__ segb = seg + b * L_;

        __syncthreads();   // protect bnd from previous iteration's readers
        if (t <= TOK_PER_BLK) {
            // lower_bound: first index i with segb[i] >= (j0 + t)
            const int target = j0 + t;
            int lo = 0, hi = L_;
            #pragma unroll 1
            while (lo < hi) {
                int mid = (lo + hi) >> 1;
                if (segb[mid] < target) lo = mid + 1; else hi = mid;
            }
            bnd[t] = lo;
        }
        __syncthreads();

        const float4* __restrict__ xb =
            reinterpret_cast<const float4*>(x + (size_t)b * L_ * H_);
        float4* __restrict__ ob =
            reinterpret_cast<float4*>(out + (size_t)b * L_ * H_);

        const int s0 = bnd[0];
        const int s1 = bnd[TOK_PER_BLK];

        int j = 0;

        // tokens empty at the very start (bnd[j+1] == s0) -> zero rows
        #pragma unroll 1
        while (j < TOK_PER_BLK && bnd[j + 1] == s0) {
            ob[(size_t)(j0 + j) * H4 + t] = make_float4(0.f, 0.f, 0.f, 0.f);
            j++;
        }

        float4 acc = make_float4(0.f, 0.f, 0.f, 0.f);

        // stream contiguous rows [s0, s1) in chunks of CH independent loads
        #pragma unroll 1
        for (int base = s0; base < s1; base += CH) {
            const int n = min(CH, s1 - base);

            float4 v[CH];
            #pragma unroll
            for (int i = 0; i < CH; i++)
                if (i < n)
                    v[i] = __ldg(&xb[(size_t)(base + i) * H4 + t]);

            #pragma unroll
            for (int i = 0; i < CH; i++) {
                if (i < n) {
                    acc.x += v[i].x; acc.y += v[i].y;
                    acc.z += v[i].z; acc.w += v[i].w;
                    const int pos1 = base + i + 1;
                    // flush every token ending exactly here (empty tokens
                    // store zero since acc resets between equal boundaries)
                    #pragma unroll 1
                    while (j < TOK_PER_BLK && bnd[j + 1] == pos1) {
                        ob[(size_t)(j0 + j) * H4 + t] = acc;
                        acc = make_float4(0.f, 0.f, 0.f, 0.f);
                        j++;
                    }
                }
            }
        }
    }
}

extern "C" void kernel_launch(void* const* d_in, const int* in_sizes, int n_in,
                              void* d_out, int out_size)
{
    const float* x   = (const float*)d_in[0];   // sequence_output  [B, L, H] f32
    const int*   seg = (const int*)  d_in[1];   // wordpiece_to_token [B, L] i32
    float*       out = (float*)d_out;           // [B, L, H] f32

    dim3 grid(GRID_BLOCKS);                     // 740 blocks = 1 wave
    dim3 block(H4);                             // 192 threads
    token_segment_sum_kernel<<<grid, block>>>(x, seg, out);
}

// round 8
// speedup vs baseline: 1.1860x; 1.0886x over previous
#include <cuda_runtime.h>
#include <stdint.h>

// Problem constants: B=16, L=4096, H=768 (fp32)
#define B_ 16
#define L_ 4096
#define H_ 768
#define H4 (H_ / 4)            // 192 float4 lanes per row
#define TOK_PER_BLK 16         // tokens per block tile
#define CH 6                   // rows prefetched per chunk
#define BLOCKS_PER_BATCH (L_ / TOK_PER_BLK)  // 256

__global__ __launch_bounds__(H4, 7)
void token_segment_sum_kernel(const float* __restrict__ x,
                              const int*   __restrict__ seg,
                              float*       __restrict__ out)
{
    const int b    = blockIdx.x / BLOCKS_PER_BATCH;
    const int tile = blockIdx.x % BLOCKS_PER_BATCH;
    const int j0   = tile * TOK_PER_BLK;

    const int* __restrict__ segb = seg + b * L_;

    __shared__ int bnd[TOK_PER_BLK + 1];

    const int t = threadIdx.x;   // 0..191 (float4 lane)
    if (t <= TOK_PER_BLK) {
        // lower_bound: first index i with segb[i] >= (j0 + t)
        const int target = j0 + t;
        int lo = 0, hi = L_;
        #pragma unroll 1
        while (lo < hi) {
            int mid = (lo + hi) >> 1;
            if (segb[mid] < target) lo = mid + 1; else hi = mid;
        }
        bnd[t] = lo;
    }
    __syncthreads();

    const float4* __restrict__ xb =
        reinterpret_cast<const float4*>(x + (size_t)b * L_ * H_);
    float4* __restrict__ ob =
        reinterpret_cast<float4*>(out + (size_t)b * L_ * H_);

    const int s0 = bnd[0];
    const int s1 = bnd[TOK_PER_BLK];

    int j = 0;

    // tokens empty at the very start (bnd[j+1] == s0) -> zero rows
    #pragma unroll 1
    while (j < TOK_PER_BLK && bnd[j + 1] == s0) {
        ob[(size_t)(j0 + j) * H4 + t] = make_float4(0.f, 0.f, 0.f, 0.f);
        j++;
    }

    // register-cached next boundary: common row path has NO shared-mem read
    int nb = (j < TOK_PER_BLK) ? bnd[j + 1] : -1;

    float4 acc = make_float4(0.f, 0.f, 0.f, 0.f);

    // stream contiguous rows [s0, s1) in chunks of CH independent loads
    #pragma unroll 1
    for (int base = s0; base < s1; base += CH) {
        const int n = min(CH, s1 - base);

        float4 v[CH];
        #pragma unroll
        for (int i = 0; i < CH; i++)
            if (i < n)
                v[i] = __ldg(&xb[(size_t)(base + i) * H4 + t]);

        #pragma unroll
        for (int i = 0; i < CH; i++) {
            if (i < n) {
                acc.x += v[i].x; acc.y += v[i].y;
                acc.z += v[i].z; acc.w += v[i].w;
                const int pos1 = base + i + 1;
                if (pos1 == nb) {          // rare path: token(s) end here
                    do {
                        ob[(size_t)(j0 + j) * H4 + t] = acc;
                        acc = make_float4(0.f, 0.f, 0.f, 0.f);
                        j++;
                        nb = (j < TOK_PER_BLK) ? bnd[j + 1] : -1;
                    } while (nb == pos1);  // consecutive equal bounds = empties
                }
            }
        }
    }
}

extern "C" void kernel_launch(void* const* d_in, const int* in_sizes, int n_in,
                              void* d_out, int out_size)
{
    const float* x   = (const float*)d_in[0];   // sequence_output  [B, L, H] f32
    const int*   seg = (const int*)  d_in[1];   // wordpiece_to_token [B, L] i32
    float*       out = (float*)d_out;           // [B, L, H] f32

    dim3 grid(B_ * BLOCKS_PER_BATCH);           // 4096 blocks
    dim3 block(H4);                             // 192 threads
    token_segment_sum_kernel<<<grid, block>>>(x, seg, out);
}